// round 15
// baseline (speedup 1.0000x reference)
#include <cuda_runtime.h>
#include <cuda_bf16.h>
#include <cstdint>

// Problem constants
#define B_   16
#define T_   8
#define E_   2048
#define H_   16
#define HD_  128
#define S_   4096
#define ST_  4104            // S_ + T_
#define BT_  128             // B_*T_
#define NSPLIT 16
#define KPS  256             // keys per split = S_/NSPLIT
#define SPLITK 8
#define NATTN 4096           // attn work items
#define NKVB 64              // fused kv-gemm blocks (2 m x 32 n)
#define SCALE_ 0.08838834764831845f  // hd^-0.5

// Output layout (floats): [out (B,T,E)][k (B,H,ST,HD)][v (B,H,ST,HD)]
#define OFF_K   262144
#define OFF_V   134742016
#define OFF_K4  65536        // OFF_K/4
#define OFF_V4  33685504     // OFF_V/4

// Scratch (static device globals; no allocation allowed)
__device__ float d_q[BT_ * E_];                       // (b,h,t,d), pre-scaled
__device__ float d_part_o[B_*H_*NSPLIT*T_*HD_];       // (blk,t,d)
__device__ float d_part_m[B_*H_*NSPLIT*T_];
__device__ float d_part_l[B_*H_*NSPLIT*T_];
__device__ float d_attn[BT_ * E_];                    // (b,t, h*HD+d)
__device__ float d_p1[SPLITK*128*2048];               // q / out gemm partials
__device__ float d_p2[SPLITK*128*2048];               // out gemm partials

typedef unsigned long long ULL;

__device__ __forceinline__ ULL pack2(float x, float y) {
    ULL r; asm("mov.b64 %0, {%1,%2};" : "=l"(r) : "f"(x), "f"(y)); return r;
}
__device__ __forceinline__ void ffma2(ULL& d, ULL a, ULL b) {
    asm("fma.rn.f32x2 %0, %1, %2, %0;" : "+l"(d) : "l"(a), "l"(b));
}
__device__ __forceinline__ void mul2(ULL& d, ULL a, ULL b) {
    asm("mul.rn.f32x2 %0, %1, %2;" : "=l"(d) : "l"(a), "l"(b));
}
__device__ __forceinline__ void unpack2(ULL v, float& x, float& y) {
    asm("mov.b64 {%0,%1}, %2;" : "=f"(x), "=f"(y) : "l"(v));
}

// ---------------------------------------------------------------------------
// GEMM (split-K): part[split][128][Npart] = A[128, kslice] @ W[:, ncols]
// BM=128, BN=128, BK=16, 256 threads, 8x8 micro-tile via FFMA2.
// ldw4 = W row stride in float4. A_ext==nullptr -> d_attn. use_p2 -> d_p2.
// ---------------------------------------------------------------------------
__global__ __launch_bounds__(256) void gemm128(
    const float* __restrict__ A_ext, const float* __restrict__ W,
    int Npart, int K, int ldw4, int use_p2)
{
    __shared__ __align__(16) float As[16*132];   // As[k][m], stride 132
    __shared__ __align__(16) float Bs[16*136];   // Bs[k][n], stride 136

    const float* __restrict__ A = A_ext ? A_ext : (const float*)d_attn;
    float* part = use_p2 ? d_p2 : d_p1;

    const int tid = threadIdx.x;
    const int tx = tid & 15, ty = tid >> 4;
    const int n0 = blockIdx.x * 128;
    const int kchunk = K / SPLITK;
    const int k0 = blockIdx.y * kchunk;
    const int kiters = kchunk / 16;

    const int Kf4 = K >> 2;
    const float4* A4 = (const float4*)A;
    const float4* W4 = (const float4*)W;

    const int r = tid >> 2, q = tid & 3;

    ULL acc[8][4];
    #pragma unroll
    for (int m = 0; m < 8; m++)
        #pragma unroll
        for (int np = 0; np < 4; np++) acc[m][np] = 0ULL;

    float4 ra0 = A4[(size_t)r*Kf4 + (k0 >> 2) + q];
    float4 ra1 = A4[(size_t)(r + 64)*Kf4 + (k0 >> 2) + q];
    float4 rb0 = W4[(size_t)(k0 + ty)*ldw4 + (n0 >> 2) + tx*2];
    float4 rb1 = W4[(size_t)(k0 + ty)*ldw4 + (n0 >> 2) + tx*2 + 1];

    for (int kt = 0; kt < kiters; kt++) {
        As[(q*4+0)*132 + r] = ra0.x;
        As[(q*4+1)*132 + r] = ra0.y;
        As[(q*4+2)*132 + r] = ra0.z;
        As[(q*4+3)*132 + r] = ra0.w;
        As[(q*4+0)*132 + 64 + r] = ra1.x;
        As[(q*4+1)*132 + 64 + r] = ra1.y;
        As[(q*4+2)*132 + 64 + r] = ra1.z;
        As[(q*4+3)*132 + 64 + r] = ra1.w;
        ((float4*)Bs)[ty*34 + tx*2]     = rb0;
        ((float4*)Bs)[ty*34 + tx*2 + 1] = rb1;
        __syncthreads();

        if (kt + 1 < kiters) {
            int kb = k0 + (kt + 1)*16;
            ra0 = A4[(size_t)r*Kf4 + (kb >> 2) + q];
            ra1 = A4[(size_t)(r + 64)*Kf4 + (kb >> 2) + q];
            rb0 = W4[(size_t)(kb + ty)*ldw4 + (n0 >> 2) + tx*2];
            rb1 = W4[(size_t)(kb + ty)*ldw4 + (n0 >> 2) + tx*2 + 1];
        }

        #pragma unroll
        for (int k = 0; k < 16; k++) {
            float4 alo = *(const float4*)&As[k*132 + ty*8];
            float4 ahi = *(const float4*)&As[k*132 + ty*8 + 4];
            float4 blo = *(const float4*)&Bs[k*136 + tx*8];
            float4 bhi = *(const float4*)&Bs[k*136 + tx*8 + 4];
            ULL bp0 = pack2(blo.x, blo.y), bp1 = pack2(blo.z, blo.w);
            ULL bp2 = pack2(bhi.x, bhi.y), bp3 = pack2(bhi.z, bhi.w);
            float am[8] = {alo.x, alo.y, alo.z, alo.w, ahi.x, ahi.y, ahi.z, ahi.w};
            #pragma unroll
            for (int m = 0; m < 8; m++) {
                ULL as = pack2(am[m], am[m]);
                ffma2(acc[m][0], as, bp0);
                ffma2(acc[m][1], as, bp1);
                ffma2(acc[m][2], as, bp2);
                ffma2(acc[m][3], as, bp3);
            }
        }
        __syncthreads();
    }

    float* pbase = part + (size_t)blockIdx.y*128*Npart;
    #pragma unroll
    for (int m = 0; m < 8; m++) {
        int row = ty*8 + m;
        float2* p2 = (float2*)(pbase + (size_t)row*Npart + n0 + tx*8);
        #pragma unroll
        for (int np = 0; np < 4; np++)
            p2[np] = *(float2*)&acc[m][np];
    }
}

// ---------------------------------------------------------------------------
// Reduce q partials: sum 8 splits + bias, scale, write d_q.
// Two half-grid launches (blk0 = 0, 128) keep the fused kernel at ncu idx 3.
// ---------------------------------------------------------------------------
__global__ __launch_bounds__(256) void reduce_q(
    const float* __restrict__ bias, int blk0)
{
    const int idx = (blk0 + blockIdx.x)*256 + threadIdx.x;    // 0..65535 f4
    const int m = idx >> 9, c4 = idx & 511;
    const float4* p4 = (const float4*)d_p1;
    float4 s = p4[idx];
    #pragma unroll
    for (int sp = 1; sp < SPLITK; sp++) {
        float4 tt = p4[sp*65536 + idx];
        s.x += tt.x; s.y += tt.y; s.z += tt.z; s.w += tt.w;
    }
    float4 bv = ((const float4*)bias)[c4];
    s.x = (s.x + bv.x) * SCALE_;
    s.y = (s.y + bv.y) * SCALE_;
    s.z = (s.z + bv.z) * SCALE_;
    s.w = (s.w + bv.w) * SCALE_;

    const int n = c4*4;                    // < 2048: always q
    const int h = n >> 7, d = n & 127;
    const int b = m >> 3, t = m & 7;
    ((float4*)d_q)[((b*H_ + h)*T_ + t)*32 + (d >> 2)] = s;
}

// ---------------------------------------------------------------------------
// Reduce out-proj partials: sum 8 splits + bias -> out[0 .. 128*2048)
// ---------------------------------------------------------------------------
__global__ __launch_bounds__(256) void reduce_out(
    const float* __restrict__ bias, float* __restrict__ out)
{
    const int idx = blockIdx.x*256 + threadIdx.x;    // 0..65535
    const float4* p4 = (const float4*)d_p2;
    float4 s = p4[idx];
    #pragma unroll
    for (int sp = 1; sp < SPLITK; sp++) {
        float4 tt = p4[sp*65536 + idx];
        s.x += tt.x; s.y += tt.y; s.z += tt.z; s.w += tt.w;
    }
    const int c4 = idx & 511;
    float4 bv = ((const float4*)bias)[c4];
    s.x += bv.x; s.y += bv.y; s.z += bv.z; s.w += bv.w;
    ((float4*)out)[idx] = s;
}

// ---------------------------------------------------------------------------
// FUSED kernel: blocks [0,4096) = attn_partial v8 (unchanged from R14);
// blocks [4096,4160) = K/V projection GEMM (BM=64, BN=128, K=2048 full,
// bias fused, scatter direct to out rows S..S+T-1). The gemm blocks are
// scheduled after the attn blocks and fill attention's idle issue slots /
// tail wave. Output regions are disjoint (attn: rows 0..4095; gemm: 4096+).
// ---------------------------------------------------------------------------
__global__ __launch_bounds__(256, 3) void attn_kv_fused(
    const float* __restrict__ ck, const float* __restrict__ cv,
    const float* __restrict__ x,  const float* __restrict__ w_qkv,
    const float* __restrict__ b_qkv, float* __restrict__ out)
{
    __shared__ __align__(16) float4 smem[2048];          // 32KB, aliased per branch

    const int tid  = threadIdx.x;

    if (blockIdx.x < NATTN) {
        // ================= attention branch (R14 v8) =================
        float4* kbuf = smem;                                 // r*33+c
        float4* q4s  = smem + 1056;                          // t*33+c
        float*  fb   = (float*)(smem + 1320);
        float*  s_sh = fb;                                   // t*33+j
        float*  p_sh = fb + 264;                             // stride 36
        float*  a_sh = fb + 264 + 288;

        const int blk   = blockIdx.x;
        const int bh    = blk >> 4;
        const int split = blk & 15;
        const int w     = tid >> 5;
        const int lane  = tid & 31;

        const float4* ck4 = (const float4*)ck;
        const float4* cv4 = (const float4*)cv;
        float4* out4 = (float4*)out;

        q4s[w*33 + lane] = ((const float4*)d_q)[(size_t)bh*256 + w*32 + lane];

        const int s_base = split * KPS;
        const int sj = 4*w + (lane & 3);
        const int st = lane >> 2;

        float m_cur = -1e30f, l_cur = 0.0f;
        ULL o_acc[T_][2];
        #pragma unroll
        for (int t = 0; t < T_; t++) { o_acc[t][0] = 0ULL; o_acc[t][1] = 0ULL; }

        float4 kk[4], vv[4];
        #pragma unroll
        for (int i = 0; i < 4; i++) {
            size_t src = ((size_t)bh*S_ + s_base + 4*w + i)*32 + lane;
            kk[i] = ck4[src]; vv[i] = cv4[src];
        }

        #pragma unroll
        for (int tile = 0; tile < 8; tile++) {
            const int s0 = s_base + tile*32;

            #pragma unroll
            for (int i = 0; i < 4; i++) {
                int r = 4*w + i;
                kbuf[r*33 + lane] = kk[i];
                out4[OFF_K4 + ((size_t)bh*ST_ + s0 + r)*32 + lane] = kk[i];
            }
            __syncthreads();   // barA

            if (tile < 7) {
                #pragma unroll
                for (int i = 0; i < 4; i++)
                    kk[i] = ck4[((size_t)bh*S_ + s0 + 32 + 4*w + i)*32 + lane];
            }

            {
                ULL acc0 = 0ULL, acc1 = 0ULL;
                #pragma unroll
                for (int c = 0; c < 32; c++) {
                    float4 kv = kbuf[sj*33 + c];
                    float4 qq = q4s[st*33 + c];
                    ffma2(acc0, pack2(kv.x, kv.y), pack2(qq.x, qq.y));
                    ffma2(acc1, pack2(kv.z, kv.w), pack2(qq.z, qq.w));
                }
                float a0x, a0y, a1x, a1y;
                unpack2(acc0, a0x, a0y);
                unpack2(acc1, a1x, a1y);
                s_sh[st*33 + sj] = (a0x + a0y) + (a1x + a1y);
            }
            __syncthreads();   // barB

            {
                float sc = s_sh[w*33 + lane];
                float mt = sc;
                #pragma unroll
                for (int off = 16; off; off >>= 1)
                    mt = fmaxf(mt, __shfl_xor_sync(0xffffffffu, mt, off));
                float m_new = fmaxf(m_cur, mt);
                float p = __expf(sc - m_new);
                float ps = p;
                #pragma unroll
                for (int off = 16; off; off >>= 1)
                    ps += __shfl_xor_sync(0xffffffffu, ps, off);
                float al = __expf(m_cur - m_new);
                l_cur = l_cur*al + ps;
                m_cur = m_new;
                p_sh[w*36 + lane] = p;
                if (lane == 0) a_sh[w] = al;
            }
            __syncthreads();   // barC

            {
                float4 al0 = *(const float4*)&a_sh[0];
                float4 al1 = *(const float4*)&a_sh[4];
                float alv[8] = {al0.x, al0.y, al0.z, al0.w,
                                al1.x, al1.y, al1.z, al1.w};
                #pragma unroll
                for (int t = 0; t < T_; t++) {
                    ULL alp = pack2(alv[t], alv[t]);
                    mul2(o_acc[t][0], o_acc[t][0], alp);
                    mul2(o_acc[t][1], o_acc[t][1], alp);
                    float4 pv = *(const float4*)&p_sh[t*36 + 4*w];
                    ffma2(o_acc[t][0], pack2(pv.x, pv.x), pack2(vv[0].x, vv[0].y));
                    ffma2(o_acc[t][1], pack2(pv.x, pv.x), pack2(vv[0].z, vv[0].w));
                    ffma2(o_acc[t][0], pack2(pv.y, pv.y), pack2(vv[1].x, vv[1].y));
                    ffma2(o_acc[t][1], pack2(pv.y, pv.y), pack2(vv[1].z, vv[1].w));
                    ffma2(o_acc[t][0], pack2(pv.z, pv.z), pack2(vv[2].x, vv[2].y));
                    ffma2(o_acc[t][1], pack2(pv.z, pv.z), pack2(vv[2].z, vv[2].w));
                    ffma2(o_acc[t][0], pack2(pv.w, pv.w), pack2(vv[3].x, vv[3].y));
                    ffma2(o_acc[t][1], pack2(pv.w, pv.w), pack2(vv[3].z, vv[3].w));
                }
            }
            #pragma unroll
            for (int i = 0; i < 4; i++)
                out4[OFF_V4 + ((size_t)bh*ST_ + s0 + 4*w + i)*32 + lane] = vv[i];
            if (tile < 7) {
                #pragma unroll
                for (int i = 0; i < 4; i++)
                    vv[i] = cv4[((size_t)bh*S_ + s0 + 32 + 4*w + i)*32 + lane];
            }
        }

        __syncthreads();
        #pragma unroll
        for (int t = 0; t < T_; t++) {
            float x0, x1, x2, x3;
            unpack2(o_acc[t][0], x0, x1);
            unpack2(o_acc[t][1], x2, x3);
            smem[(w*T_ + t)*32 + lane] = make_float4(x0, x1, x2, x3);
        }
        __syncthreads();
        {
            float4 osum = make_float4(0.f, 0.f, 0.f, 0.f);
            #pragma unroll
            for (int sw = 0; sw < 8; sw++) {
                float4 v = smem[(sw*T_ + w)*32 + lane];
                osum.x += v.x; osum.y += v.y; osum.z += v.z; osum.w += v.w;
            }
            ((float4*)d_part_o)[((size_t)blk*T_ + w)*32 + lane] = osum;
            if (lane == 0) {
                d_part_m[blk*T_ + w] = m_cur;
                d_part_l[blk*T_ + w] = l_cur;
            }
        }
    } else {
        // ================= K/V projection branch =================
        // C[64,128] = x[64 rows, 2048] @ w_qkv[:, n0..n0+128) + bias
        float* Asf = (float*)smem;             // [16][68]  4352B
        float* Bsf = (float*)smem + 16*68;     // [16][136] 8704B

        const int idx = blockIdx.x - NATTN;    // 0..63
        const int m0 = (idx & 1) * 64;
        const int nb = idx >> 1;               // 0..31
        const int n0 = 2048 + nb*128;          // global col in w_qkv

        const int tx = tid & 15, ty = tid >> 4;
        const int lm = tid >> 2, kq = tid & 3;

        const float4* x4 = (const float4*)x;       // row stride 512 f4
        const float4* w4 = (const float4*)w_qkv;   // row stride 1536 f4

        ULL acc[4][4];
        #pragma unroll
        for (int i = 0; i < 4; i++)
            #pragma unroll
            for (int j = 0; j < 4; j++) acc[i][j] = 0ULL;

        float4 ra  = x4[(size_t)(m0 + lm)*512 + kq];
        float4 rb0 = w4[(size_t)ty*1536 + (n0 >> 2) + tx*2];
        float4 rb1 = w4[(size_t)ty*1536 + (n0 >> 2) + tx*2 + 1];

        for (int kt = 0; kt < 128; kt++) {
            Asf[(kq*4+0)*68 + lm] = ra.x;
            Asf[(kq*4+1)*68 + lm] = ra.y;
            Asf[(kq*4+2)*68 + lm] = ra.z;
            Asf[(kq*4+3)*68 + lm] = ra.w;
            ((float4*)Bsf)[ty*34 + tx*2]     = rb0;
            ((float4*)Bsf)[ty*34 + tx*2 + 1] = rb1;
            __syncthreads();

            if (kt + 1 < 128) {
                ra  = x4[(size_t)(m0 + lm)*512 + (kt+1)*4 + kq];
                rb0 = w4[(size_t)((kt+1)*16 + ty)*1536 + (n0 >> 2) + tx*2];
                rb1 = w4[(size_t)((kt+1)*16 + ty)*1536 + (n0 >> 2) + tx*2 + 1];
            }

            #pragma unroll
            for (int k = 0; k < 16; k++) {
                float4 a   = *(const float4*)&Asf[k*68 + ty*4];
                float4 blo = *(const float4*)&Bsf[k*136 + tx*8];
                float4 bhi = *(const float4*)&Bsf[k*136 + tx*8 + 4];
                ULL bp0 = pack2(blo.x, blo.y), bp1 = pack2(blo.z, blo.w);
                ULL bp2 = pack2(bhi.x, bhi.y), bp3 = pack2(bhi.z, bhi.w);
                float am[4] = {a.x, a.y, a.z, a.w};
                #pragma unroll
                for (int i = 0; i < 4; i++) {
                    ULL as = pack2(am[i], am[i]);
                    ffma2(acc[i][0], as, bp0);
                    ffma2(acc[i][1], as, bp1);
                    ffma2(acc[i][2], as, bp2);
                    ffma2(acc[i][3], as, bp3);
                }
            }
            __syncthreads();
        }

        // epilogue: bias + scatter to out k/v rows S..S+T-1
        const size_t base = (nb < 16) ? (size_t)OFF_K : (size_t)OFF_V;
        #pragma unroll
        for (int i = 0; i < 4; i++) {
            const int m = m0 + ty*4 + i;
            const int b = m >> 3, t = m & 7;
            #pragma unroll
            for (int j = 0; j < 4; j++) {
                float lo, hi;
                unpack2(acc[i][j], lo, hi);
                const int n = n0 + tx*8 + 2*j;
                const int e = n & 2047;
                const int h = e >> 7, d = e & 127;
                lo += b_qkv[n];
                hi += b_qkv[n + 1];
                float2* dst = (float2*)&out[base +
                    ((size_t)((b*H_ + h)*ST_ + S_ + t))*HD_ + d];
                *dst = make_float2(lo, hi);
            }
        }
    }
}

// ---------------------------------------------------------------------------
// K3: combine 16 split partials + causal-masked new keys.
// grid 512 x 128: warp handles one (bh,t) task.
// ---------------------------------------------------------------------------
__global__ __launch_bounds__(128) void attn_combine(const float* __restrict__ out_ro)
{
    const int task = blockIdx.x*4 + (threadIdx.x >> 5);   // 0..2047
    const int bh   = task >> 3;
    const int t    = task & 7;
    const int lane = threadIdx.x & 31;

    const float4* q4 = (const float4*)d_q;
    const float4* o4 = (const float4*)out_ro;
    const float4* po4 = (const float4*)d_part_o;

    float4 qv = q4[(size_t)(bh*T_ + t)*32 + lane];

    float sj[T_];
    float m_new = -1e30f;
    #pragma unroll
    for (int j = 0; j < T_; j++) {
        float sc = -1e30f;
        if (j <= t) {
            float4 kv = o4[OFF_K4 + ((size_t)bh*ST_ + S_ + j)*32 + lane];
            float p = qv.x*kv.x + qv.y*kv.y + qv.z*kv.z + qv.w*kv.w;
            #pragma unroll
            for (int off = 16; off; off >>= 1)
                p += __shfl_xor_sync(0xffffffffu, p, off);
            sc = p;
        }
        sj[j] = sc;
        m_new = fmaxf(m_new, sc);
    }

    float pm[NSPLIT], pl[NSPLIT];
    #pragma unroll
    for (int s = 0; s < NSPLIT; s++) {
        pm[s] = d_part_m[(bh*NSPLIT + s)*T_ + t];
        pl[s] = d_part_l[(bh*NSPLIT + s)*T_ + t];
        m_new = fmaxf(m_new, pm[s]);
    }

    float denom = 0.0f;
    float4 acc = make_float4(0.f, 0.f, 0.f, 0.f);
    #pragma unroll
    for (int s = 0; s < NSPLIT; s++) {
        float ws = __expf(pm[s] - m_new);
        denom += ws * pl[s];
        float4 po = po4[((size_t)(bh*NSPLIT + s)*T_ + t)*32 + lane];
        acc.x = fmaf(ws, po.x, acc.x);
        acc.y = fmaf(ws, po.y, acc.y);
        acc.z = fmaf(ws, po.z, acc.z);
        acc.w = fmaf(ws, po.w, acc.w);
    }
    #pragma unroll
    for (int j = 0; j < T_; j++) {
        if (j <= t) {
            float p = __expf(sj[j] - m_new);
            denom += p;
            float4 vv = o4[OFF_V4 + ((size_t)bh*ST_ + S_ + j)*32 + lane];
            acc.x = fmaf(p, vv.x, acc.x);
            acc.y = fmaf(p, vv.y, acc.y);
            acc.z = fmaf(p, vv.z, acc.z);
            acc.w = fmaf(p, vv.w, acc.w);
        }
    }

    float inv = 1.0f / denom;
    acc.x *= inv; acc.y *= inv; acc.z *= inv; acc.w *= inv;

    float4* a4 = (float4*)d_attn;
    int b = bh >> 4, h = bh & 15;
    a4[((size_t)(b*T_ + t))*512 + h*32 + lane] = acc;
}

// ---------------------------------------------------------------------------
extern "C" void kernel_launch(void* const* d_in, const int* in_sizes, int n_in,
                              void* d_out, int out_size)
{
    const float* x      = (const float*)d_in[0];
    const float* ck     = (const float*)d_in[1];
    const float* cv     = (const float*)d_in[2];
    const float* w_qkv  = (const float*)d_in[3];
    const float* b_qkv  = (const float*)d_in[4];
    const float* w_out  = (const float*)d_in[5];
    const float* b_out  = (const float*)d_in[6];
    float* out = (float*)d_out;

    // q-projection only (n < 2048), split-K
    gemm128<<<dim3(16, SPLITK), 256>>>(x, w_qkv, 2048, 2048, 1536, 0); // launch 0
    reduce_q<<<128, 256>>>(b_qkv, 0);                                  // launch 1
    reduce_q<<<128, 256>>>(b_qkv, 128);                                // launch 2
    // fused: attention (+cache copy) and K/V projection
    attn_kv_fused<<<NATTN + NKVB, 256>>>(ck, cv, x, w_qkv, b_qkv, out);// launch 3 (ncu)
    attn_combine<<<512, 128>>>(out);                                   // launch 4
    gemm128<<<dim3(16, SPLITK), 256>>>(nullptr, w_out, 2048, 2048, 512, 1);
    reduce_out<<<256, 256>>>(b_out, out);
}

// round 16
// speedup vs baseline: 1.5238x; 1.5238x over previous
#include <cuda_runtime.h>
#include <cuda_bf16.h>
#include <cstdint>

// Problem constants
#define B_   16
#define T_   8
#define E_   2048
#define H_   16
#define HD_  128
#define S_   4096
#define ST_  4104            // S_ + T_
#define BT_  128             // B_*T_
#define NSPLIT 16
#define KPS  256             // keys per split = S_/NSPLIT
#define SPLITK 8
#define NATTN 4096           // attn work items
#define NKVB 128             // fused kv-gemm blocks (2 m x 64 n), BM=64 BN=64
#define SCALE_ 0.08838834764831845f  // hd^-0.5

// Output layout (floats): [out (B,T,E)][k (B,H,ST,HD)][v (B,H,ST,HD)]
#define OFF_K   262144
#define OFF_V   134742016
#define OFF_K4  65536        // OFF_K/4
#define OFF_V4  33685504     // OFF_V/4

// Scratch (static device globals; no allocation allowed)
__device__ float d_q[BT_ * E_];                       // (b,h,t,d), pre-scaled
__device__ float d_part_o[B_*H_*NSPLIT*T_*HD_];       // (blk,t,d)
__device__ float d_part_m[B_*H_*NSPLIT*T_];
__device__ float d_part_l[B_*H_*NSPLIT*T_];
__device__ float d_attn[BT_ * E_];                    // (b,t, h*HD+d)
__device__ float d_p1[SPLITK*128*2048];               // q gemm partials
__device__ float d_p2[SPLITK*128*2048];               // out gemm partials

typedef unsigned long long ULL;

__device__ __forceinline__ ULL pack2(float x, float y) {
    ULL r; asm("mov.b64 %0, {%1,%2};" : "=l"(r) : "f"(x), "f"(y)); return r;
}
__device__ __forceinline__ void ffma2(ULL& d, ULL a, ULL b) {
    asm("fma.rn.f32x2 %0, %1, %2, %0;" : "+l"(d) : "l"(a), "l"(b));
}
__device__ __forceinline__ void mul2(ULL& d, ULL a, ULL b) {
    asm("mul.rn.f32x2 %0, %1, %2;" : "=l"(d) : "l"(a), "l"(b));
}
__device__ __forceinline__ void unpack2(ULL v, float& x, float& y) {
    asm("mov.b64 {%0,%1}, %2;" : "=f"(x), "=f"(y) : "l"(v));
}

// ---------------------------------------------------------------------------
// GEMM (split-K): part[split][128][Npart] = A[128, kslice] @ W[:, ncols]
// BM=128, BN=128, BK=16, 256 threads, 8x8 micro-tile via FFMA2.
// ---------------------------------------------------------------------------
__global__ __launch_bounds__(256) void gemm128(
    const float* __restrict__ A_ext, const float* __restrict__ W,
    int Npart, int K, int ldw4, int use_p2)
{
    __shared__ __align__(16) float As[16*132];   // As[k][m], stride 132
    __shared__ __align__(16) float Bs[16*136];   // Bs[k][n], stride 136

    const float* __restrict__ A = A_ext ? A_ext : (const float*)d_attn;
    float* part = use_p2 ? d_p2 : d_p1;

    const int tid = threadIdx.x;
    const int tx = tid & 15, ty = tid >> 4;
    const int n0 = blockIdx.x * 128;
    const int kchunk = K / SPLITK;
    const int k0 = blockIdx.y * kchunk;
    const int kiters = kchunk / 16;

    const int Kf4 = K >> 2;
    const float4* A4 = (const float4*)A;
    const float4* W4 = (const float4*)W;

    const int r = tid >> 2, q = tid & 3;

    ULL acc[8][4];
    #pragma unroll
    for (int m = 0; m < 8; m++)
        #pragma unroll
        for (int np = 0; np < 4; np++) acc[m][np] = 0ULL;

    float4 ra0 = A4[(size_t)r*Kf4 + (k0 >> 2) + q];
    float4 ra1 = A4[(size_t)(r + 64)*Kf4 + (k0 >> 2) + q];
    float4 rb0 = W4[(size_t)(k0 + ty)*ldw4 + (n0 >> 2) + tx*2];
    float4 rb1 = W4[(size_t)(k0 + ty)*ldw4 + (n0 >> 2) + tx*2 + 1];

    for (int kt = 0; kt < kiters; kt++) {
        As[(q*4+0)*132 + r] = ra0.x;
        As[(q*4+1)*132 + r] = ra0.y;
        As[(q*4+2)*132 + r] = ra0.z;
        As[(q*4+3)*132 + r] = ra0.w;
        As[(q*4+0)*132 + 64 + r] = ra1.x;
        As[(q*4+1)*132 + 64 + r] = ra1.y;
        As[(q*4+2)*132 + 64 + r] = ra1.z;
        As[(q*4+3)*132 + 64 + r] = ra1.w;
        ((float4*)Bs)[ty*34 + tx*2]     = rb0;
        ((float4*)Bs)[ty*34 + tx*2 + 1] = rb1;
        __syncthreads();

        if (kt + 1 < kiters) {
            int kb = k0 + (kt + 1)*16;
            ra0 = A4[(size_t)r*Kf4 + (kb >> 2) + q];
            ra1 = A4[(size_t)(r + 64)*Kf4 + (kb >> 2) + q];
            rb0 = W4[(size_t)(kb + ty)*ldw4 + (n0 >> 2) + tx*2];
            rb1 = W4[(size_t)(kb + ty)*ldw4 + (n0 >> 2) + tx*2 + 1];
        }

        #pragma unroll
        for (int k = 0; k < 16; k++) {
            float4 alo = *(const float4*)&As[k*132 + ty*8];
            float4 ahi = *(const float4*)&As[k*132 + ty*8 + 4];
            float4 blo = *(const float4*)&Bs[k*136 + tx*8];
            float4 bhi = *(const float4*)&Bs[k*136 + tx*8 + 4];
            ULL bp0 = pack2(blo.x, blo.y), bp1 = pack2(blo.z, blo.w);
            ULL bp2 = pack2(bhi.x, bhi.y), bp3 = pack2(bhi.z, bhi.w);
            float am[8] = {alo.x, alo.y, alo.z, alo.w, ahi.x, ahi.y, ahi.z, ahi.w};
            #pragma unroll
            for (int m = 0; m < 8; m++) {
                ULL as = pack2(am[m], am[m]);
                ffma2(acc[m][0], as, bp0);
                ffma2(acc[m][1], as, bp1);
                ffma2(acc[m][2], as, bp2);
                ffma2(acc[m][3], as, bp3);
            }
        }
        __syncthreads();
    }

    float* pbase = part + (size_t)blockIdx.y*128*Npart;
    #pragma unroll
    for (int m = 0; m < 8; m++) {
        int row = ty*8 + m;
        float2* p2 = (float2*)(pbase + (size_t)row*Npart + n0 + tx*8);
        #pragma unroll
        for (int np = 0; np < 4; np++)
            p2[np] = *(float2*)&acc[m][np];
    }
}

// ---------------------------------------------------------------------------
// Reduce q partials: sum 8 splits + bias, scale, write d_q.
// Two half-grid launches (blk0 = 0, 128) keep the fused kernel at ncu idx 3.
// ---------------------------------------------------------------------------
__global__ __launch_bounds__(256) void reduce_q(
    const float* __restrict__ bias, int blk0)
{
    const int idx = (blk0 + blockIdx.x)*256 + threadIdx.x;    // 0..65535 f4
    const int m = idx >> 9, c4 = idx & 511;
    const float4* p4 = (const float4*)d_p1;
    float4 s = p4[idx];
    #pragma unroll
    for (int sp = 1; sp < SPLITK; sp++) {
        float4 tt = p4[sp*65536 + idx];
        s.x += tt.x; s.y += tt.y; s.z += tt.z; s.w += tt.w;
    }
    float4 bv = ((const float4*)bias)[c4];
    s.x = (s.x + bv.x) * SCALE_;
    s.y = (s.y + bv.y) * SCALE_;
    s.z = (s.z + bv.z) * SCALE_;
    s.w = (s.w + bv.w) * SCALE_;

    const int n = c4*4;                    // < 2048: always q
    const int h = n >> 7, d = n & 127;
    const int b = m >> 3, t = m & 7;
    ((float4*)d_q)[((b*H_ + h)*T_ + t)*32 + (d >> 2)] = s;
}

// ---------------------------------------------------------------------------
// Reduce out-proj partials: sum 8 splits + bias -> out[0 .. 128*2048)
// ---------------------------------------------------------------------------
__global__ __launch_bounds__(256) void reduce_out(
    const float* __restrict__ bias, float* __restrict__ out)
{
    const int idx = blockIdx.x*256 + threadIdx.x;    // 0..65535
    const float4* p4 = (const float4*)d_p2;
    float4 s = p4[idx];
    #pragma unroll
    for (int sp = 1; sp < SPLITK; sp++) {
        float4 tt = p4[sp*65536 + idx];
        s.x += tt.x; s.y += tt.y; s.z += tt.z; s.w += tt.w;
    }
    const int c4 = idx & 511;
    float4 bv = ((const float4*)bias)[c4];
    s.x += bv.x; s.y += bv.y; s.z += bv.z; s.w += bv.w;
    ((float4*)out)[idx] = s;
}

// ---------------------------------------------------------------------------
// FUSED kernel: blocks [0, NKVB) = K/V projection GEMM, BM=64 x BN=64,
// LOW register micro-tile (acc[4][2] = ~50 regs, NO spill under the 80-reg
// budget). Blocks [NKVB, NKVB+4096) = attn_partial v8 (exact R14 code).
// Gemm blocks come FIRST so they overlap the bulk attention phase (R15's
// back-placement ran them serially on an empty machine, spilled at 88 regs).
// Output regions are disjoint (gemm: rows S..S+T-1; attn: rows 0..S-1).
// ---------------------------------------------------------------------------
__global__ __launch_bounds__(256, 3) void attn_kv_fused(
    const float* __restrict__ ck, const float* __restrict__ cv,
    const float* __restrict__ x,  const float* __restrict__ w_qkv,
    const float* __restrict__ b_qkv, float* __restrict__ out)
{
    __shared__ __align__(16) float4 smem[2048];          // 32KB, aliased per branch

    const int tid  = threadIdx.x;

    if (blockIdx.x >= NKVB) {
        // ================= attention branch (exact R14 v8) =================
        float4* kbuf = smem;                                 // r*33+c
        float4* q4s  = smem + 1056;                          // t*33+c
        float*  fb   = (float*)(smem + 1320);
        float*  s_sh = fb;                                   // t*33+j
        float*  p_sh = fb + 264;                             // stride 36
        float*  a_sh = fb + 264 + 288;

        const int blk   = blockIdx.x - NKVB;
        const int bh    = blk >> 4;
        const int split = blk & 15;
        const int w     = tid >> 5;
        const int lane  = tid & 31;

        const float4* ck4 = (const float4*)ck;
        const float4* cv4 = (const float4*)cv;
        float4* out4 = (float4*)out;

        q4s[w*33 + lane] = ((const float4*)d_q)[(size_t)bh*256 + w*32 + lane];

        const int s_base = split * KPS;
        const int sj = 4*w + (lane & 3);
        const int st = lane >> 2;

        float m_cur = -1e30f, l_cur = 0.0f;
        ULL o_acc[T_][2];
        #pragma unroll
        for (int t = 0; t < T_; t++) { o_acc[t][0] = 0ULL; o_acc[t][1] = 0ULL; }

        float4 kk[4], vv[4];
        #pragma unroll
        for (int i = 0; i < 4; i++) {
            size_t src = ((size_t)bh*S_ + s_base + 4*w + i)*32 + lane;
            kk[i] = ck4[src]; vv[i] = cv4[src];
        }

        #pragma unroll
        for (int tile = 0; tile < 8; tile++) {
            const int s0 = s_base + tile*32;

            #pragma unroll
            for (int i = 0; i < 4; i++) {
                int r = 4*w + i;
                kbuf[r*33 + lane] = kk[i];
                out4[OFF_K4 + ((size_t)bh*ST_ + s0 + r)*32 + lane] = kk[i];
            }
            __syncthreads();   // barA

            if (tile < 7) {
                #pragma unroll
                for (int i = 0; i < 4; i++)
                    kk[i] = ck4[((size_t)bh*S_ + s0 + 32 + 4*w + i)*32 + lane];
            }

            {
                ULL acc0 = 0ULL, acc1 = 0ULL;
                #pragma unroll
                for (int c = 0; c < 32; c++) {
                    float4 kv = kbuf[sj*33 + c];
                    float4 qq = q4s[st*33 + c];
                    ffma2(acc0, pack2(kv.x, kv.y), pack2(qq.x, qq.y));
                    ffma2(acc1, pack2(kv.z, kv.w), pack2(qq.z, qq.w));
                }
                float a0x, a0y, a1x, a1y;
                unpack2(acc0, a0x, a0y);
                unpack2(acc1, a1x, a1y);
                s_sh[st*33 + sj] = (a0x + a0y) + (a1x + a1y);
            }
            __syncthreads();   // barB

            {
                float sc = s_sh[w*33 + lane];
                float mt = sc;
                #pragma unroll
                for (int off = 16; off; off >>= 1)
                    mt = fmaxf(mt, __shfl_xor_sync(0xffffffffu, mt, off));
                float m_new = fmaxf(m_cur, mt);
                float p = __expf(sc - m_new);
                float ps = p;
                #pragma unroll
                for (int off = 16; off; off >>= 1)
                    ps += __shfl_xor_sync(0xffffffffu, ps, off);
                float al = __expf(m_cur - m_new);
                l_cur = l_cur*al + ps;
                m_cur = m_new;
                p_sh[w*36 + lane] = p;
                if (lane == 0) a_sh[w] = al;
            }
            __syncthreads();   // barC

            {
                float4 al0 = *(const float4*)&a_sh[0];
                float4 al1 = *(const float4*)&a_sh[4];
                float alv[8] = {al0.x, al0.y, al0.z, al0.w,
                                al1.x, al1.y, al1.z, al1.w};
                #pragma unroll
                for (int t = 0; t < T_; t++) {
                    ULL alp = pack2(alv[t], alv[t]);
                    mul2(o_acc[t][0], o_acc[t][0], alp);
                    mul2(o_acc[t][1], o_acc[t][1], alp);
                    float4 pv = *(const float4*)&p_sh[t*36 + 4*w];
                    ffma2(o_acc[t][0], pack2(pv.x, pv.x), pack2(vv[0].x, vv[0].y));
                    ffma2(o_acc[t][1], pack2(pv.x, pv.x), pack2(vv[0].z, vv[0].w));
                    ffma2(o_acc[t][0], pack2(pv.y, pv.y), pack2(vv[1].x, vv[1].y));
                    ffma2(o_acc[t][1], pack2(pv.y, pv.y), pack2(vv[1].z, vv[1].w));
                    ffma2(o_acc[t][0], pack2(pv.z, pv.z), pack2(vv[2].x, vv[2].y));
                    ffma2(o_acc[t][1], pack2(pv.z, pv.z), pack2(vv[2].z, vv[2].w));
                    ffma2(o_acc[t][0], pack2(pv.w, pv.w), pack2(vv[3].x, vv[3].y));
                    ffma2(o_acc[t][1], pack2(pv.w, pv.w), pack2(vv[3].z, vv[3].w));
                }
            }
            #pragma unroll
            for (int i = 0; i < 4; i++)
                out4[OFF_V4 + ((size_t)bh*ST_ + s0 + 4*w + i)*32 + lane] = vv[i];
            if (tile < 7) {
                #pragma unroll
                for (int i = 0; i < 4; i++)
                    vv[i] = cv4[((size_t)bh*S_ + s0 + 32 + 4*w + i)*32 + lane];
            }
        }

        __syncthreads();
        #pragma unroll
        for (int t = 0; t < T_; t++) {
            float x0, x1, x2, x3;
            unpack2(o_acc[t][0], x0, x1);
            unpack2(o_acc[t][1], x2, x3);
            smem[(w*T_ + t)*32 + lane] = make_float4(x0, x1, x2, x3);
        }
        __syncthreads();
        {
            float4 osum = make_float4(0.f, 0.f, 0.f, 0.f);
            #pragma unroll
            for (int sw = 0; sw < 8; sw++) {
                float4 v = smem[(sw*T_ + w)*32 + lane];
                osum.x += v.x; osum.y += v.y; osum.z += v.z; osum.w += v.w;
            }
            ((float4*)d_part_o)[((size_t)blk*T_ + w)*32 + lane] = osum;
            if (lane == 0) {
                d_part_m[blk*T_ + w] = m_cur;
                d_part_l[blk*T_ + w] = l_cur;
            }
        }
    } else {
        // ============ K/V projection branch (BM=64, BN=64, ~50 regs) ========
        // C[64,64] = x[m0..m0+64, 0:2048] @ w_qkv[:, n0..n0+64) + bias
        float* Asf = (float*)smem;             // [16][68]  4352B
        float* Bsf = (float*)smem + 16*68;     // [16][72]  4608B

        const int idx = blockIdx.x;            // 0..127
        const int m0 = (idx & 1) * 64;
        const int nb = idx >> 1;               // 0..63
        const int n0 = 2048 + nb*64;           // global col in w_qkv

        const int tx = tid & 15, ty = tid >> 4;

        const float4* x4 = (const float4*)x;       // row stride 512 f4
        const float4* w4 = (const float4*)w_qkv;   // row stride 1536 f4

        ULL acc[4][2];
        #pragma unroll
        for (int i = 0; i < 4; i++) { acc[i][0] = 0ULL; acc[i][1] = 0ULL; }

        // loads: A tile 64x16 = 1 f4/thread (row=tid>>2 of 64, kq=tid&3);
        //        B tile 16x64 = 1 f4/thread (row=ty, col4=tx)
        const int lm = tid >> 2, kq = tid & 3;

        float4 ra = x4[(size_t)(m0 + lm)*512 + kq];
        float4 rb = w4[(size_t)ty*1536 + (n0 >> 2) + tx];

        for (int kt = 0; kt < 128; kt++) {
            Asf[(kq*4+0)*68 + lm] = ra.x;
            Asf[(kq*4+1)*68 + lm] = ra.y;
            Asf[(kq*4+2)*68 + lm] = ra.z;
            Asf[(kq*4+3)*68 + lm] = ra.w;
            *(float4*)&Bsf[ty*72 + tx*4] = rb;
            __syncthreads();

            if (kt + 1 < 128) {
                ra = x4[(size_t)(m0 + lm)*512 + (kt+1)*4 + kq];
                rb = w4[(size_t)((kt+1)*16 + ty)*1536 + (n0 >> 2) + tx];
            }

            #pragma unroll
            for (int k = 0; k < 16; k++) {
                float4 a = *(const float4*)&Asf[k*68 + ty*4];
                ULL bp0 = *(const ULL*)&Bsf[k*72 + tx*4];
                ULL bp1 = *(const ULL*)&Bsf[k*72 + tx*4 + 2];
                ULL a0 = pack2(a.x, a.x);
                ULL a1 = pack2(a.y, a.y);
                ULL a2 = pack2(a.z, a.z);
                ULL a3 = pack2(a.w, a.w);
                ffma2(acc[0][0], a0, bp0); ffma2(acc[0][1], a0, bp1);
                ffma2(acc[1][0], a1, bp0); ffma2(acc[1][1], a1, bp1);
                ffma2(acc[2][0], a2, bp0); ffma2(acc[2][1], a2, bp1);
                ffma2(acc[3][0], a3, bp0); ffma2(acc[3][1], a3, bp1);
            }
            __syncthreads();
        }

        // epilogue: bias + scatter to out k/v rows S..S+T-1
        const size_t base = (nb < 32) ? (size_t)OFF_K : (size_t)OFF_V;
        #pragma unroll
        for (int i = 0; i < 4; i++) {
            const int m = m0 + ty*4 + i;
            const int b = m >> 3, t = m & 7;
            #pragma unroll
            for (int j = 0; j < 2; j++) {
                float lo, hi;
                unpack2(acc[i][j], lo, hi);
                const int n = n0 + tx*4 + 2*j;
                const int e = n & 2047;
                const int h = e >> 7, d = e & 127;
                lo += b_qkv[n];
                hi += b_qkv[n + 1];
                float2* dst = (float2*)&out[base +
                    ((size_t)((b*H_ + h)*ST_ + S_ + t))*HD_ + d];
                *dst = make_float2(lo, hi);
            }
        }
    }
}

// ---------------------------------------------------------------------------
// K3: combine 16 split partials + causal-masked new keys.
// grid 512 x 128: warp handles one (bh,t) task.
// ---------------------------------------------------------------------------
__global__ __launch_bounds__(128) void attn_combine(const float* __restrict__ out_ro)
{
    const int task = blockIdx.x*4 + (threadIdx.x >> 5);   // 0..2047
    const int bh   = task >> 3;
    const int t    = task & 7;
    const int lane = threadIdx.x & 31;

    const float4* q4 = (const float4*)d_q;
    const float4* o4 = (const float4*)out_ro;
    const float4* po4 = (const float4*)d_part_o;

    float4 qv = q4[(size_t)(bh*T_ + t)*32 + lane];

    float sj[T_];
    float m_new = -1e30f;
    #pragma unroll
    for (int j = 0; j < T_; j++) {
        float sc = -1e30f;
        if (j <= t) {
            float4 kv = o4[OFF_K4 + ((size_t)bh*ST_ + S_ + j)*32 + lane];
            float p = qv.x*kv.x + qv.y*kv.y + qv.z*kv.z + qv.w*kv.w;
            #pragma unroll
            for (int off = 16; off; off >>= 1)
                p += __shfl_xor_sync(0xffffffffu, p, off);
            sc = p;
        }
        sj[j] = sc;
        m_new = fmaxf(m_new, sc);
    }

    float pm[NSPLIT], pl[NSPLIT];
    #pragma unroll
    for (int s = 0; s < NSPLIT; s++) {
        pm[s] = d_part_m[(bh*NSPLIT + s)*T_ + t];
        pl[s] = d_part_l[(bh*NSPLIT + s)*T_ + t];
        m_new = fmaxf(m_new, pm[s]);
    }

    float denom = 0.0f;
    float4 acc = make_float4(0.f, 0.f, 0.f, 0.f);
    #pragma unroll
    for (int s = 0; s < NSPLIT; s++) {
        float ws = __expf(pm[s] - m_new);
        denom += ws * pl[s];
        float4 po = po4[((size_t)(bh*NSPLIT + s)*T_ + t)*32 + lane];
        acc.x = fmaf(ws, po.x, acc.x);
        acc.y = fmaf(ws, po.y, acc.y);
        acc.z = fmaf(ws, po.z, acc.z);
        acc.w = fmaf(ws, po.w, acc.w);
    }
    #pragma unroll
    for (int j = 0; j < T_; j++) {
        if (j <= t) {
            float p = __expf(sj[j] - m_new);
            denom += p;
            float4 vv = o4[OFF_V4 + ((size_t)bh*ST_ + S_ + j)*32 + lane];
            acc.x = fmaf(p, vv.x, acc.x);
            acc.y = fmaf(p, vv.y, acc.y);
            acc.z = fmaf(p, vv.z, acc.z);
            acc.w = fmaf(p, vv.w, acc.w);
        }
    }

    float inv = 1.0f / denom;
    acc.x *= inv; acc.y *= inv; acc.z *= inv; acc.w *= inv;

    float4* a4 = (float4*)d_attn;
    int b = bh >> 4, h = bh & 15;
    a4[((size_t)(b*T_ + t))*512 + h*32 + lane] = acc;
}

// ---------------------------------------------------------------------------
extern "C" void kernel_launch(void* const* d_in, const int* in_sizes, int n_in,
                              void* d_out, int out_size)
{
    const float* x      = (const float*)d_in[0];
    const float* ck     = (const float*)d_in[1];
    const float* cv     = (const float*)d_in[2];
    const float* w_qkv  = (const float*)d_in[3];
    const float* b_qkv  = (const float*)d_in[4];
    const float* w_out  = (const float*)d_in[5];
    const float* b_out  = (const float*)d_in[6];
    float* out = (float*)d_out;

    // q-projection only (n < 2048), split-K
    gemm128<<<dim3(16, SPLITK), 256>>>(x, w_qkv, 2048, 2048, 1536, 0); // launch 0
    reduce_q<<<128, 256>>>(b_qkv, 0);                                  // launch 1
    reduce_q<<<128, 256>>>(b_qkv, 128);                                // launch 2
    // fused: K/V projection (first 128 blocks) + attention (+cache copy)
    attn_kv_fused<<<NKVB + NATTN, 256>>>(ck, cv, x, w_qkv, b_qkv, out);// launch 3 (ncu)
    attn_combine<<<512, 128>>>(out);                                   // launch 4
    gemm128<<<dim3(16, SPLITK), 256>>>(nullptr, w_out, 2048, 2048, 512, 1);
    reduce_out<<<256, 256>>>(b_out, out);
}